// round 14
// baseline (speedup 1.0000x reference)
#include <cuda_runtime.h>

// SoftMSMLoss: soft-MSM DP, gamma=1, c=1, 512x512, B=64.
// Probability-domain wavefront (P = e^{-C} as per-element (mantissa, int exp)),
// 64 blocks x 512 threads (16 warps, 1 row/thread). Boundary handoff uses a
// poison-word protocol: the packed 32-bit value IS the flag (no fences, no
// chunk polls). hand[0] prefilled with zero-prob words makes warp 0 uniform.

#define TLEN 512
#define NW 16
#define NBATCH 64
#define PAD 32
#define HLEN (TLEN + 2 * PAD)  // 576
#define NSTEP 543              // lane31 computes j=511 at s=542
#define LOG2E 1.4426950408889634f
#define LN2 0.6931471805599453f
#define KCONST 0.36787944117144233f  // e^{-c}, c=1
#define SENT (-8192)
#define EXPBIAS 16384
#define PACK_ZERO 0x00002000u   // sv=1.0, mi=SENT  -> P ~ 0
#define POISON 0xFFFFFFFFu      // unreachable pack (mi would be +49151)
#define GATE_T 1e-3f

__device__ float g_costs[NBATCH];
__device__ int g_done;

__device__ __forceinline__ float scale2(int d) {  // 2^d, d<=0, underflow->0
    int bb = 127 + d;
    bb = max(bb, 0);
    return __int_as_float(bb << 23);
}
__device__ __forceinline__ unsigned packp(float sv, int mi) {
    const unsigned frac = (__float_as_uint(sv) >> 7) & 0xFFFFu;
    return (frac << 16) | (unsigned)(mi + EXPBIAS);
}

__global__ __launch_bounds__(512, 1) void soft_msm_kernel(
    const float* __restrict__ x, const float* __restrict__ y,
    float* __restrict__ out) {
    __shared__ float4 scol[HLEN];        // {y_j, dyb_j, Eb_j, K*Eb_j}
    __shared__ unsigned hand[NW][HLEN];  // hand[w] = boundary INTO warp w

    const int t = threadIdx.x;  // row index
    const int w = t >> 5;
    const int l = t & 31;
    const int b = blockIdx.x;
    const float* xb = x + b * TLEN;
    const float* yb = y + b * TLEN;

    // column constants + pads
    for (int i = t; i < HLEN; i += 512) {
        const int j = i - PAD;
        if (j > 0 && j < TLEN) {
            const float yv = yb[j];
            const float dyb = yv - yb[j - 1];
            const float eb = exp2f(-LOG2E * dyb * dyb);
            scol[i] = make_float4(yv, dyb, eb, eb * KCONST);
        } else if (j == 0) {
            scol[i] = make_float4(yb[0], 1e9f, 0.0f, 0.0f);
        } else {  // pad: benign finite values
            scol[i] = make_float4(0.0f, 2.0f, 0.5f, 0.5f * KCONST);
        }
    }
    // hand init: row 0 all PACK_ZERO (uniform warp-0 path); rows 1..15:
    // POISON in the live region [PAD, PAD+512), PACK_ZERO in the high pad
    // (read by consumers for j>511), low pad value irrelevant (never read).
    for (int i = t; i < NW * HLEN; i += 512) {
        const int ww = i / HLEN;
        const int j = (i % HLEN) - PAD;
        unsigned v = PACK_ZERO;
        if (ww > 0 && j >= 0 && j < TLEN) v = POISON;
        hand[ww][i % HLEN] = v;
    }
    const float xi = xb[t];
    float myDxa, myEa, myEaK;
    if (t > 0) {
        myDxa = xi - xb[t - 1];
        myEa = exp2f(-LOG2E * myDxa * myDxa);
        myEaK = myEa * KCONST;
    } else {
        myDxa = 1e9f;
        myEa = 0.0f;
        myEaK = 0.0f;
    }
    __syncthreads();

    float svC = 0.0f;  // own P(row, j-1)
    int miC = SENT;
    float svD = (t == 0) ? 1.0f : 0.0f;  // rolling up -> diag
    int miD_ = (t == 0) ? 0 : SENT;
    const bool isCons = (l == 0);
    const bool isProd = (l == 31) && (w < NW - 1);
    volatile const unsigned* consPtr = &hand[w][PAD];  // reads col j = s
    unsigned* prodPtr = &hand[0][0] + (w + 1) * HLEN + (PAD - 31);  // col s-31

#pragma unroll 8
    for (int s = 0; s < NSTEP; ++s) {
        float svU = __shfl_up_sync(0xffffffffu, svC, 1);
        int miU = __shfl_up_sync(0xffffffffu, miC, 1);
        if (isCons) {  // data-is-the-flag: spin only while POISON
            unsigned u = consPtr[s];
            while (u == POISON) {
                __nanosleep(40);
                u = consPtr[s];
            }
            svU = __uint_as_float(0x3F800000u | ((u & 0xFFFF0000u) >> 9));
            miU = (int)(u & 0xFFFFu) - EXPBIAS;
        }
        const float dgS = svD;
        const int dgM = miD_;
        svD = svU;
        miD_ = miU;

        const float4 cv = scol[PAD - l + s];
        const float bm = xi - cv.x;
        const float matchp = (LOG2E * bm) * bm;
        const float Em = exp2f(-matchp);
        const float EmK = Em * KCONST;

        const float uu = myDxa * bm;
        const float ul = -cv.y * bm;
        float selU = (uu > 0.0f) ? (myEaK + EmK) : KCONST;
        float selL = (ul > 0.0f) ? (cv.w + EmK) : KCONST;
        if (fminf(fabsf(uu), fabsf(ul)) < GATE_T) {  // exact gate, rare
            const float wu = 0.5f + 0.5f * uu * rsqrtf(uu * uu + 1e-9f);
            selU = KCONST * exp2f(wu * __log2f(myEa + Em));
            const float wl = 0.5f + 0.5f * ul * rsqrtf(ul * ul + 1e-9f);
            selL = KCONST * exp2f(wl * __log2f(cv.z + Em));
        }

        const float tD = dgS * Em;
        const float tU = svU * selU;
        const float tL = svC * selL;
        const int mh = max(dgM, max(miU, miC));
        const float ssum =
            fmaf(tD, scale2(dgM - mh),
                 fmaf(tU, scale2(miU - mh), tL * scale2(miC - mh)));
        const int sb = __float_as_int(ssum);
        svC = __int_as_float((sb & 0x007FFFFF) | 0x3F800000);
        miC = mh + ((sb >> 23) - 127);

        if (isProd) prodPtr[s] = packp(svC, miC);  // bare STS; word = flag
    }

    if (t == TLEN - 1) {  // C(511,511) computed at s=542
        g_costs[b] = -((float)miC + __log2f(svC)) * LN2;
        __threadfence();
        const int old = atomicAdd(&g_done, 1);
        if (old == NBATCH - 1) {
            __threadfence();
            float v = 0.0f;
#pragma unroll
            for (int i = 0; i < NBATCH; ++i) v += g_costs[i];
            out[0] = v * (1.0f / (float)NBATCH);
            atomicExch(&g_done, 0);
        }
    }
}

extern "C" void kernel_launch(void* const* d_in, const int* in_sizes, int n_in,
                              void* d_out, int out_size) {
    const float* x = (const float*)d_in[0];
    const float* y = (const float*)d_in[1];
    float* out = (float*)d_out;
    soft_msm_kernel<<<NBATCH, 512>>>(x, y, out);
}

// round 15
// speedup vs baseline: 1.0345x; 1.0345x over previous
#include <cuda_runtime.h>

// SoftMSMLoss: soft-MSM DP, gamma=1, c=1, 512x512, B=64.
// Probability-domain wavefront (P = e^{-C} as per-element (mantissa, int exp)),
// 64 blocks x 512 threads (16 warps, 1 row/thread). Chunked-flag handoff with
// 128-bit vectorized boundary transfers (1 LDS.128 / 1 STS.128 per 4 steps),
// uniform warp-0 path via prefilled hand[0]/flags[0].

#define TLEN 512
#define NW 16
#define NBATCH 64
#define PAD 32
#define HLEN (TLEN + 2 * PAD)  // 576
#define NSTEP 543              // lane31 computes j=511 at s=542
#define LOG2E 1.4426950408889634f
#define LN2 0.6931471805599453f
#define KCONST 0.36787944117144233f  // e^{-c}, c=1
#define SENT (-8192)
#define EXPBIAS 16384
#define PACK_ZERO 0x00002000u  // sv=1.0, mi=SENT -> P ~ 0
#define GATE_T 1e-3f

__device__ float g_costs[NBATCH];
__device__ int g_done;

__device__ __forceinline__ float scale2(int d) {  // 2^d, d<=0, underflow->0
    int bb = 127 + d;
    bb = max(bb, 0);
    return __int_as_float(bb << 23);
}
__device__ __forceinline__ unsigned packp(float sv, int mi) {
    const unsigned frac = (__float_as_uint(sv) >> 7) & 0xFFFFu;
    return (frac << 16) | (unsigned)(mi + EXPBIAS);
}

__global__ __launch_bounds__(512, 1) void soft_msm_kernel(
    const float* __restrict__ x, const float* __restrict__ y,
    float* __restrict__ out) {
    __shared__ float4 scol[HLEN];  // {y_j, dyb_j, Eb_j, K*Eb_j}
    __shared__ __align__(16) unsigned hand[NW][HLEN];  // boundary INTO warp w
    __shared__ volatile int flags[NW];  // flags[w]: cols available to warp w

    const int t = threadIdx.x;  // row index
    const int w = t >> 5;
    const int l = t & 31;
    const int b = blockIdx.x;
    const float* xb = x + b * TLEN;
    const float* yb = y + b * TLEN;

    if (t < NW) flags[t] = (t == 0) ? (1 << 20) : 0;
    // column constants + pads
    for (int i = t; i < HLEN; i += 512) {
        const int j = i - PAD;
        if (j > 0 && j < TLEN) {
            const float yv = yb[j];
            const float dyb = yv - yb[j - 1];
            const float eb = exp2f(-LOG2E * dyb * dyb);
            scol[i] = make_float4(yv, dyb, eb, eb * KCONST);
        } else if (j == 0) {
            scol[i] = make_float4(yb[0], 1e9f, 0.0f, 0.0f);
        } else {  // pad: benign finite values
            scol[i] = make_float4(0.0f, 2.0f, 0.5f, 0.5f * KCONST);
        }
    }
    // hand prefill: row 0 = PACK_ZERO everywhere (uniform warp-0 path);
    // rows >0: PACK_ZERO in high pad (read for j>511); rest don't-care.
    for (int i = t; i < NW * HLEN; i += 512) hand[0][i] = PACK_ZERO;

    const float xi = xb[t];
    float myDxa, myEa, myEaK;
    if (t > 0) {
        myDxa = xi - xb[t - 1];
        myEa = exp2f(-LOG2E * myDxa * myDxa);
        myEaK = myEa * KCONST;
    } else {
        myDxa = 1e9f;
        myEa = 0.0f;
        myEaK = 0.0f;
    }
    __syncthreads();

    float svC = 0.0f;  // own P(row, j-1)
    int miC = SENT;
    float svD = (t == 0) ? 1.0f : 0.0f;  // rolling up -> diag
    int miD_ = (t == 0) ? 0 : SENT;
    const bool isCons = (l == 0);
    const bool isProd = (l == 31) && (w < NW - 1);
    const uint4* consVec = (const uint4*)&hand[w][PAD];     // col group s/4
    uint4* prodVec = (uint4*)&hand[0][0] + ((w + 1) * HLEN + PAD - 32) / 4;
    int availS = 0;
    uint4 gc = make_uint4(PACK_ZERO, PACK_ZERO, PACK_ZERO, PACK_ZERO);
    uint4 pp;

#pragma unroll 8
    for (int s = 0; s < NSTEP; ++s) {
        // consumer: refill 4-col register buffer (s % 4 == 0)
        if ((s & 3) == 0) {
            if (isCons) {
                const int need = (s + 4 < TLEN) ? (s + 4) : TLEN;
                if (availS < need) {
                    while ((availS = flags[w]) < need) __nanosleep(20);
                    __threadfence_block();
                }
                gc = consVec[s >> 2];
            }
        }

        float svU = __shfl_up_sync(0xffffffffu, svC, 1);
        int miU = __shfl_up_sync(0xffffffffu, miC, 1);
        if (isCons) {
            unsigned u;
            switch (s & 3) {  // compile-time under unroll
                case 0: u = gc.x; break;
                case 1: u = gc.y; break;
                case 2: u = gc.z; break;
                default: u = gc.w; break;
            }
            svU = __uint_as_float(0x3F800000u | ((u & 0xFFFF0000u) >> 9));
            miU = (int)(u & 0xFFFFu) - EXPBIAS;
        }
        const float dgS = svD;
        const int dgM = miD_;
        svD = svU;
        miD_ = miU;

        const float4 cv = scol[PAD - l + s];
        const float bm = xi - cv.x;
        const float matchp = (LOG2E * bm) * bm;
        const float Em = exp2f(-matchp);
        const float EmK = Em * KCONST;

        const float uu = myDxa * bm;
        const float ul = -cv.y * bm;
        float selU = (uu > 0.0f) ? (myEaK + EmK) : KCONST;
        float selL = (ul > 0.0f) ? (cv.w + EmK) : KCONST;
        if (fminf(fabsf(uu), fabsf(ul)) < GATE_T) {  // exact gate, rare
            const float wu = 0.5f + 0.5f * uu * rsqrtf(uu * uu + 1e-9f);
            selU = KCONST * exp2f(wu * __log2f(myEa + Em));
            const float wl = 0.5f + 0.5f * ul * rsqrtf(ul * ul + 1e-9f);
            selL = KCONST * exp2f(wl * __log2f(cv.z + Em));
        }

        const float tD = dgS * Em;
        const float tU = svU * selU;
        const float tL = svC * selL;
        const int mh = max(dgM, max(miU, miC));
        const float ssum =
            fmaf(tD, scale2(dgM - mh),
                 fmaf(tU, scale2(miU - mh), tL * scale2(miC - mh)));
        const int sb = __float_as_int(ssum);
        svC = __int_as_float((sb & 0x007FFFFF) | 0x3F800000);
        miC = mh + ((sb >> 23) - 127);

        // producer: j = s - 31; slot = j & 3 = (s+1) & 3 (compile-time)
        if (isProd) {
            const unsigned pk = packp(svC, miC);
            switch ((s + 1) & 3) {
                case 0: pp.x = pk; break;
                case 1: pp.y = pk; break;
                case 2: pp.z = pk; break;
                default: pp.w = pk; break;
            }
        }
        if (((s + 1) & 3) == 3) {  // j % 4 == 3: flush group (j<0 -> low pad)
            if (isProd) {
                const int j = s - 31;
                prodVec[(j + 32) >> 2] = pp;  // group base col j-3
                __threadfence_block();
                flags[w + 1] = j + 1;
            }
        }
    }

    if (t == TLEN - 1) {  // C(511,511) computed at s=542
        g_costs[b] = -((float)miC + __log2f(svC)) * LN2;
        __threadfence();
        const int old = atomicAdd(&g_done, 1);
        if (old == NBATCH - 1) {
            __threadfence();
            float v = 0.0f;
#pragma unroll
            for (int i = 0; i < NBATCH; ++i) v += g_costs[i];
            out[0] = v * (1.0f / (float)NBATCH);
            atomicExch(&g_done, 0);
        }
    }
}

extern "C" void kernel_launch(void* const* d_in, const int* in_sizes, int n_in,
                              void* d_out, int out_size) {
    const float* x = (const float*)d_in[0];
    const float* y = (const float*)d_in[1];
    float* out = (float*)d_out;
    soft_msm_kernel<<<NBATCH, 512>>>(x, y, out);
}

// round 17
// speedup vs baseline: 1.0423x; 1.0075x over previous
#include <cuda_runtime.h>

// SoftMSMLoss: soft-MSM DP, gamma=1, c=1, 512x512, B=64.
// Probability-domain wavefront (P = e^{-C} per-element (mantissa, int exp)),
// 64 blocks x 512 threads (16 warps, 1 row/thread). Vectorized boundary
// handoff (LDS.128/STS.128 per 4 steps) with MANUAL x4 phase unrolling so all
// component selection folds at compile time. Uniform warp-0 path.

#define TLEN 512
#define NW 16
#define NBATCH 64
#define PAD 32
#define HLEN (TLEN + 2 * PAD)  // 576
#define LOG2E 1.4426950408889634f
#define LN2 0.6931471805599453f
#define KCONST 0.36787944117144233f  // e^{-c}, c=1
#define SENT (-8192)
#define EXPBIAS 16384
#define PACK_ZERO 0x00002000u  // sv=1.0, mi=SENT -> P ~ 0
#define GATE_T 1e-3f

__device__ float g_costs[NBATCH];
__device__ int g_done;

__device__ __forceinline__ float scale2(int d) {  // 2^d, d<=0, underflow->0
    int bb = 127 + d;
    bb = max(bb, 0);
    return __int_as_float(bb << 23);
}
__device__ __forceinline__ unsigned packp(float sv, int mi) {
    const unsigned frac = (__float_as_uint(sv) >> 7) & 0xFFFFu;
    return (frac << 16) | (unsigned)(mi + EXPBIAS);
}

// One wavefront step at compile-time phase P (s % 4 == P).
#define STEP(P, s)                                                            \
    do {                                                                      \
        if ((P) == 0 && isCons) { /* refill 4-col buffer */                   \
            const int need = min((s) + 4, TLEN);                              \
            if (availS < need) {                                              \
                while ((availS = flags[w]) < need) __nanosleep(20);           \
                __threadfence_block();                                        \
            }                                                                 \
            gc = consVec[((s) >> 2) + (PAD >> 2)];                            \
        }                                                                     \
        float svU = __shfl_up_sync(0xffffffffu, svC, 1);                      \
        int miU = __shfl_up_sync(0xffffffffu, miC, 1);                        \
        if (isCons) {                                                         \
            const unsigned u = ((P) == 0)   ? gc.x                            \
                               : ((P) == 1) ? gc.y                            \
                               : ((P) == 2) ? gc.z                            \
                                            : gc.w;                          \
            svU = __uint_as_float(0x3F800000u | ((u & 0xFFFF0000u) >> 9));    \
            miU = (int)(u & 0xFFFFu) - EXPBIAS;                               \
        }                                                                     \
        const float dgS = svD;                                                \
        const int dgM = miD_;                                                 \
        svD = svU;                                                            \
        miD_ = miU;                                                           \
        const float4 cv = scolp[(s)];                                         \
        const float bm = xi - cv.x;                                           \
        const float matchp = (LOG2E * bm) * bm;                               \
        const float Em = exp2f(-matchp);                                      \
        const float EmK = Em * KCONST;                                        \
        const float uu = myDxa * bm;                                          \
        const float ul = -cv.y * bm;                                          \
        float selU = (uu > 0.0f) ? (myEaK + EmK) : KCONST;                    \
        float selL = (ul > 0.0f) ? (cv.w + EmK) : KCONST;                     \
        if (fminf(fabsf(uu), fabsf(ul)) < GATE_T) { /* exact gate, rare */    \
            const float wu = 0.5f + 0.5f * uu * rsqrtf(uu * uu + 1e-9f);      \
            selU = KCONST * exp2f(wu * __log2f(myEa + Em));                   \
            const float wl = 0.5f + 0.5f * ul * rsqrtf(ul * ul + 1e-9f);      \
            selL = KCONST * exp2f(wl * __log2f(cv.z + Em));                   \
        }                                                                     \
        const float tD = dgS * Em;                                            \
        const float tU = svU * selU;                                          \
        const float tL = svC * selL;                                          \
        const int mh = max(dgM, max(miU, miC));                               \
        const float ssum =                                                    \
            fmaf(tD, scale2(dgM - mh),                                        \
                 fmaf(tU, scale2(miU - mh), tL * scale2(miC - mh)));          \
        const int sb = __float_as_int(ssum);                                  \
        svC = __int_as_float((sb & 0x007FFFFF) | 0x3F800000);                 \
        miC = mh + ((sb >> 23) - 127);                                        \
        if (isProd) { /* j = s-31; slot j&3 = (P+1)&3 */                      \
            const unsigned pk = packp(svC, miC);                              \
            if ((P) == 3) pp.x = pk;                                          \
            if ((P) == 0) pp.y = pk;                                          \
            if ((P) == 1) pp.z = pk;                                          \
            if ((P) == 2) {                                                   \
                pp.w = pk;                                                    \
                prodVec[((s)-2) >> 2] = pp; /* cols s-34..s-31 */             \
                __threadfence_block();                                        \
                flags[w + 1] = (s)-30;                                        \
            }                                                                 \
        }                                                                     \
    } while (0)

__global__ __launch_bounds__(512, 1) void soft_msm_kernel(
    const float* __restrict__ x, const float* __restrict__ y,
    float* __restrict__ out) {
    __shared__ float4 scol[HLEN];  // {y_j, dyb_j, Eb_j, K*Eb_j}
    __shared__ __align__(16) unsigned hand[NW][HLEN];  // boundary INTO warp w
    __shared__ volatile int flags[NW];

    const int t = threadIdx.x;  // row index
    const int w = t >> 5;
    const int l = t & 31;
    const int b = blockIdx.x;
    const float* xb = x + b * TLEN;
    const float* yb = y + b * TLEN;

    if (t < NW) flags[t] = (t == 0) ? (1 << 20) : 0;
    for (int i = t; i < HLEN; i += 512) {
        const int j = i - PAD;
        if (j > 0 && j < TLEN) {
            const float yv = yb[j];
            const float dyb = yv - yb[j - 1];
            const float eb = exp2f(-LOG2E * dyb * dyb);
            scol[i] = make_float4(yv, dyb, eb, eb * KCONST);
        } else if (j == 0) {
            scol[i] = make_float4(yb[0], 1e9f, 0.0f, 0.0f);
        } else {  // pad: benign finite values
            scol[i] = make_float4(0.0f, 2.0f, 0.5f, 0.5f * KCONST);
        }
    }
    // prefill: hand[0] all PACK_ZERO (uniform warp-0); rows>0 high pad too.
    for (int i = t; i < NW * HLEN; i += 512) hand[0][i] = PACK_ZERO;

    const float xi = xb[t];
    float myDxa, myEa, myEaK;
    if (t > 0) {
        myDxa = xi - xb[t - 1];
        myEa = exp2f(-LOG2E * myDxa * myDxa);
        myEaK = myEa * KCONST;
    } else {
        myDxa = 1e9f;
        myEa = 0.0f;
        myEaK = 0.0f;
    }
    __syncthreads();

    float svC = 0.0f;  // own P(row, j-1)
    int miC = SENT;
    float svD = (t == 0) ? 1.0f : 0.0f;  // rolling up -> diag
    int miD_ = (t == 0) ? 0 : SENT;
    const bool isCons = (l == 0);
    const bool isProd = (l == 31) && (w < NW - 1);
    const uint4* consVec = (const uint4*)&hand[w][0];
    uint4* prodVec = (isProd ? (uint4*)&hand[w + 1][0] : (uint4*)&hand[0][0]) +
                     (PAD >> 2) - 8;  // group g covers cols 4g-32..4g-29
    int availS = 0;
    uint4 gc = make_uint4(PACK_ZERO, PACK_ZERO, PACK_ZERO, PACK_ZERO);
    uint4 pp = make_uint4(PACK_ZERO, PACK_ZERO, PACK_ZERO, PACK_ZERO);
    const float4* scolp = &scol[PAD - l];

#pragma unroll 2
    for (int s0 = 0; s0 < 540; s0 += 4) {  // 135 groups of 4
        STEP(0, s0);
        STEP(1, s0 + 1);
        STEP(2, s0 + 2);
        STEP(3, s0 + 3);
    }
    // tail: s = 540, 541, 542 (phases 0,1,2); thread 511's j=511 at s=542
    STEP(0, 540);
    STEP(1, 541);
    STEP(2, 542);

    if (t == TLEN - 1) {  // C(511,511)
        g_costs[b] = -((float)miC + __log2f(svC)) * LN2;
        __threadfence();
        const int old = atomicAdd(&g_done, 1);
        if (old == NBATCH - 1) {
            __threadfence();
            float v = 0.0f;
#pragma unroll
            for (int i = 0; i < NBATCH; ++i) v += g_costs[i];
            out[0] = v * (1.0f / (float)NBATCH);
            atomicExch(&g_done, 0);
        }
    }
}

extern "C" void kernel_launch(void* const* d_in, const int* in_sizes, int n_in,
                              void* d_out, int out_size) {
    const float* x = (const float*)d_in[0];
    const float* y = (const float*)d_in[1];
    float* out = (float*)d_out;
    soft_msm_kernel<<<NBATCH, 512>>>(x, y, out);
}